// round 1
// baseline (speedup 1.0000x reference)
#include <cuda_runtime.h>
#include <math.h>

// Problem constants
#define NROWS 8192
#define IN_F  512
#define RFF   2048
#define OUT_F 1000
#define INV_RFF_SCALAR (1.0f / 32.0f)
#define MFF   25.0f

// Scratch (allocation-free rule: __device__ globals)
__device__ float g_Phi[NROWS * RFF];            // 64 MB
__device__ float g_diag_part[16 * NROWS];       // per-N-tile partial diag sums

// Tiling config
#define BM 128
#define BN 128
#define BK 8
#define TM 8
#define TN 8
#define NTHREADS 256

// MODE 0: Phi = cos(D@W + b) / 32          (A=D [M,K] rm, B=W [K,N] rm, Cout=g_Phi)
// MODE 1: diag partials from Phi@cov ∘ Phi (A=g_Phi, B=cov [K,N] rm, no Cout)
// MODE 2: out = (Phi@logit_w^T + lb) * rsqrt(1+25*diag)   (B=logit_w [N,K] rm, transposed load)
template <int MODE>
__global__ __launch_bounds__(NTHREADS)
void gp_gemm_kernel(const float* __restrict__ A, const float* __restrict__ B,
                    const float* __restrict__ bias, float* __restrict__ Cout,
                    int M, int Nn, int K)
{
    __shared__ float As[BK][BM];
    __shared__ float Bs[BK][BN + 4];
    __shared__ float sred[BM][17];   // MODE 1 deterministic row reduction (padded)

    const int t  = threadIdx.x;
    const int tx = t & 15;          // 0..15
    const int ty = t >> 4;          // 0..15
    const int rowTile = blockIdx.y * BM;
    const int colTile = blockIdx.x * BN;

    // A-tile load mapping: 128 rows x 8 k, float4 along k
    const int aRow  = t >> 1;            // 0..127
    const int aKv   = (t & 1) * 4;       // 0 or 4
    // B-tile load mapping (MODE 0/1): 8 k-rows x 128 n, float4 along n
    const int bK    = t >> 5;            // 0..7
    const int bNv   = (t & 31) * 4;      // 0..124
    // B-tile load mapping (MODE 2, transposed from logit_w [N,K]):
    const int bN2   = t >> 1;            // 0..127
    const int bK2   = (t & 1) * 4;       // 0 or 4

    const float* Aptr = A + (size_t)(rowTile + aRow) * K;

    float acc[TM][TN];
    #pragma unroll
    for (int i = 0; i < TM; i++)
        #pragma unroll
        for (int j = 0; j < TN; j++) acc[i][j] = 0.0f;

    for (int k0 = 0; k0 < K; k0 += BK) {
        // ---- load A tile (transposed into As[k][m]) ----
        float4 av = *(const float4*)(Aptr + k0 + aKv);
        As[aKv + 0][aRow] = av.x;
        As[aKv + 1][aRow] = av.y;
        As[aKv + 2][aRow] = av.z;
        As[aKv + 3][aRow] = av.w;

        // ---- load B tile ----
        if (MODE == 2) {
            const int gn = colTile + bN2;
            float4 bv = make_float4(0.f, 0.f, 0.f, 0.f);
            if (gn < Nn) bv = *(const float4*)(B + (size_t)gn * K + k0 + bK2);
            Bs[bK2 + 0][bN2] = bv.x;
            Bs[bK2 + 1][bN2] = bv.y;
            Bs[bK2 + 2][bN2] = bv.z;
            Bs[bK2 + 3][bN2] = bv.w;
        } else {
            float4 bv = *(const float4*)(B + (size_t)(k0 + bK) * Nn + colTile + bNv);
            *(float4*)&Bs[bK][bNv] = bv;
        }
        __syncthreads();

        // ---- micro-kernel ----
        #pragma unroll
        for (int kk = 0; kk < BK; kk++) {
            float a[TM], bb[TN];
            #pragma unroll
            for (int i = 0; i < TM; i++) a[i] = As[kk][ty * TM + i];
            #pragma unroll
            for (int j = 0; j < TN; j++) bb[j] = Bs[kk][tx * TN + j];
            #pragma unroll
            for (int i = 0; i < TM; i++)
                #pragma unroll
                for (int j = 0; j < TN; j++)
                    acc[i][j] = fmaf(a[i], bb[j], acc[i][j]);
        }
        __syncthreads();
    }

    // ---- epilogues ----
    if (MODE == 0) {
        #pragma unroll
        for (int i = 0; i < TM; i++) {
            const int row = rowTile + ty * TM + i;
            #pragma unroll
            for (int jv = 0; jv < TN; jv += 4) {
                const int col = colTile + tx * TN + jv;
                float4 o;
                o.x = cosf(acc[i][jv + 0] + bias[col + 0]) * INV_RFF_SCALAR;
                o.y = cosf(acc[i][jv + 1] + bias[col + 1]) * INV_RFF_SCALAR;
                o.z = cosf(acc[i][jv + 2] + bias[col + 2]) * INV_RFF_SCALAR;
                o.w = cosf(acc[i][jv + 3] + bias[col + 3]) * INV_RFF_SCALAR;
                *(float4*)(Cout + (size_t)row * Nn + col) = o;
            }
        }
    } else if (MODE == 1) {
        // rowsum over this block's N-tile of (Phi@cov) ∘ Phi
        float rowsum[TM];
        #pragma unroll
        for (int i = 0; i < TM; i++) {
            const int row = rowTile + ty * TM + i;
            const float* phiRow = A + (size_t)row * K + colTile + tx * TN;
            float s = 0.0f;
            #pragma unroll
            for (int jv = 0; jv < TN; jv += 4) {
                float4 p = *(const float4*)(phiRow + jv);
                s = fmaf(acc[i][jv + 0], p.x, s);
                s = fmaf(acc[i][jv + 1], p.y, s);
                s = fmaf(acc[i][jv + 2], p.z, s);
                s = fmaf(acc[i][jv + 3], p.w, s);
            }
            rowsum[i] = s;
        }
        #pragma unroll
        for (int i = 0; i < TM; i++) sred[ty * TM + i][tx] = rowsum[i];
        __syncthreads();
        if (t < BM) {
            float s = 0.0f;
            #pragma unroll
            for (int p = 0; p < 16; p++) s += sred[t][p];
            g_diag_part[(size_t)blockIdx.x * NROWS + rowTile + t] = s;
        }
    } else {  // MODE 2
        float scale[TM];
        #pragma unroll
        for (int i = 0; i < TM; i++) {
            const int row = rowTile + ty * TM + i;
            float dg = 0.0f;
            #pragma unroll
            for (int p = 0; p < 16; p++) dg += g_diag_part[(size_t)p * NROWS + row];
            scale[i] = rsqrtf(1.0f + MFF * dg);
        }
        #pragma unroll
        for (int i = 0; i < TM; i++) {
            const int row = rowTile + ty * TM + i;
            #pragma unroll
            for (int j = 0; j < TN; j++) {
                const int col = colTile + tx * TN + j;
                if (col < Nn)
                    Cout[(size_t)row * Nn + col] = (acc[i][j] + bias[col]) * scale[i];
            }
        }
    }
}

extern "C" void kernel_launch(void* const* d_in, const int* in_sizes, int n_in,
                              void* d_out, int out_size)
{
    const float* D   = (const float*)d_in[0];  // [8192, 512]
    const float* W   = (const float*)d_in[1];  // [512, 2048]
    const float* b   = (const float*)d_in[2];  // [2048]
    const float* lw  = (const float*)d_in[3];  // [1000, 2048]
    const float* lb  = (const float*)d_in[4];  // [1000]
    const float* cov = (const float*)d_in[5];  // [2048, 2048]
    float* out = (float*)d_out;                // [8192, 1000]

    float* Phi = nullptr;
    cudaGetSymbolAddress((void**)&Phi, g_Phi);

    dim3 block(NTHREADS);
    // GEMM1: Phi = cos(D@W + b)/32 ; M=8192 N=2048 K=512
    {
        dim3 grid(RFF / BN, NROWS / BM);
        gp_gemm_kernel<0><<<grid, block>>>(D, W, b, Phi, NROWS, RFF, IN_F);
    }
    // GEMM2: diag partials from (Phi@cov) ∘ Phi ; M=8192 N=2048 K=2048
    {
        dim3 grid(RFF / BN, NROWS / BM);
        gp_gemm_kernel<1><<<grid, block>>>(Phi, cov, nullptr, nullptr, NROWS, RFF, RFF);
    }
    // GEMM3: out = (Phi@lw^T + lb) * rsqrt(1+25*diag) ; M=8192 N=1000 K=2048
    {
        dim3 grid((OUT_F + BN - 1) / BN, NROWS / BM);
        gp_gemm_kernel<2><<<grid, block>>>(Phi, lw, lb, out, NROWS, OUT_F, RFF);
    }
}

// round 3
// speedup vs baseline: 2.9781x; 2.9781x over previous
#include <cuda_runtime.h>
#include <math.h>
#include <stdint.h>

// ---------------- problem constants ----------------
#define NROWS 8192
#define IN_F  512
#define RFF   2048
#define OUT_F 1000
#define KBIG  (3*IN_F)          // 1536: [Dhi | Dlo | Dhi] x [Whi | Whi | Wlo]
#define INV_RFF_SCALAR (1.0f/32.0f)
#define MFF   25.0f

// ---------------- tiling ----------------
#define BM 128
#define BN 128
#define BK 32
#define LDSS 36                     // smem row stride in floats (padded)
#define STAGE_FLOATS (2*128*LDSS)   // A tile + B tile = 9216 floats
#define NTH 256

// ---------------- device scratch (allocation-free rule) ----------------
__device__ float g_Phi[NROWS*RFF];            // 64 MB
__device__ float g_Abig[NROWS*KBIG];          // 48 MB
__device__ float g_Bbig[RFF*KBIG];            // 12 MB  ([N][K] layout)
__device__ float g_diag_part[16*NROWS];

// ---------------- helpers ----------------
__device__ __forceinline__ uint32_t smem_u32(const void* p) {
    uint32_t r;
    asm("{ .reg .u64 t; cvta.to.shared.u64 t, %1; cvt.u32.u64 %0, t; }" : "=r"(r) : "l"(p));
    return r;
}
__device__ __forceinline__ float to_tf32(float x) {
    float r; asm("cvt.rna.tf32.f32 %0, %1;" : "=f"(r) : "f"(x)); return r;
}
__device__ __forceinline__ void cp16(uint32_t d, const void* s, uint32_t srcsz) {
    asm volatile("cp.async.cg.shared.global [%0], [%1], 16, %2;" :: "r"(d), "l"(s), "r"(srcsz));
}
__device__ __forceinline__ void cp_commit() { asm volatile("cp.async.commit_group;"); }
template <int N> __device__ __forceinline__ void cp_wait() {
    asm volatile("cp.async.wait_group %0;" :: "n"(N));
}
__device__ __forceinline__ void mma_tf32(float* c, const uint32_t* a, const uint32_t* b) {
    asm volatile(
        "mma.sync.aligned.m16n8k8.row.col.f32.tf32.tf32.f32 "
        "{%0,%1,%2,%3}, {%4,%5,%6,%7}, {%8,%9}, {%0,%1,%2,%3};"
        : "+f"(c[0]), "+f"(c[1]), "+f"(c[2]), "+f"(c[3])
        : "r"(a[0]), "r"(a[1]), "r"(a[2]), "r"(a[3]), "r"(b[0]), "r"(b[1]));
}

// ---------------- prep kernels (tf32 hi/lo split, K-concat) ----------------
__global__ void split_D_k(const float* __restrict__ D, float* __restrict__ A) {
    int idx = blockIdx.x * blockDim.x + threadIdx.x;
    if (idx >= NROWS * IN_F) return;
    int r = idx >> 9, k = idx & (IN_F - 1);
    float x = D[idx], hi = to_tf32(x), lo = x - hi;
    float* p = A + (size_t)r * KBIG;
    p[k] = hi; p[IN_F + k] = lo; p[2 * IN_F + k] = hi;
}

__global__ void split_W_k(const float* __restrict__ W, float* __restrict__ Bb) {
    __shared__ float t[32][33];
    int nb = blockIdx.x * 32, kb = blockIdx.y * 32;
    int tx = threadIdx.x, ty0 = threadIdx.y;
    #pragma unroll
    for (int i = 0; i < 32; i += 8) {
        int ty = ty0 + i;
        t[ty][tx] = W[(size_t)(kb + ty) * RFF + nb + tx];
    }
    __syncthreads();
    #pragma unroll
    for (int i = 0; i < 32; i += 8) {
        int ty = ty0 + i;
        int n = nb + ty, k = kb + tx;
        float x = t[tx][ty], hi = to_tf32(x), lo = x - hi;
        float* p = Bb + (size_t)n * KBIG;
        p[k] = hi; p[IN_F + k] = hi; p[2 * IN_F + k] = lo;
    }
}

// ---------------- main mma.sync GEMM ----------------
// A [M,K] row-major, B [N,K] row-major (both ld = K).
// MODE 0: Phi = cos(acc + bias)/32
// MODE 1: diag partial = rowsum(acc * Phi)
// MODE 2: out = (acc + lb) * rsqrt(1 + 25*diag)
template <int MODE>
__global__ void __launch_bounds__(NTH, 2)
gp_mma(const float* __restrict__ Ag, const float* __restrict__ Bg,
       const float* __restrict__ bias, float* __restrict__ outp,
       const float* __restrict__ phi, float* __restrict__ diagp,
       int Nn, int K, int nIter)
{
    extern __shared__ float dyn[];
    const int tid = threadIdx.x;
    const int wid = tid >> 5, lane = tid & 31;
    const int g = lane >> 2, t = lane & 3;       // fragment coords
    const int warpM = wid >> 2, warpN = wid & 3; // 2x4 warp grid (64x32 warp tile)
    const int rowTile = blockIdx.y * BM, colTile = blockIdx.x * BN;
    const uint32_t sbase = smem_u32(dyn);

    float acc[4][4][4];
    #pragma unroll
    for (int mt = 0; mt < 4; mt++)
        #pragma unroll
        for (int nt = 0; nt < 4; nt++)
            #pragma unroll
            for (int r = 0; r < 4; r++) acc[mt][nt][r] = 0.0f;

    // copy mapping: 1024 float4 per matrix per stage; 4 per thread each
    const int cr = (tid * 4 + 0) >> 5 == 0 ? 0 : 0; (void)cr;

    #define ISSUE(it, s) do {                                                    \
        const int _k0 = (it) * BK;                                               \
        _Pragma("unroll")                                                        \
        for (int j = 0; j < 4; j++) {                                            \
            int f = tid + NTH * j;                                               \
            int r = f >> 3, q = f & 7;                                           \
            uint32_t d = sbase + (uint32_t)((s) * STAGE_FLOATS + r * LDSS + q * 4) * 4; \
            cp16(d, Ag + (size_t)(rowTile + r) * K + _k0 + q * 4, 16);           \
        }                                                                        \
        _Pragma("unroll")                                                        \
        for (int j = 0; j < 4; j++) {                                            \
            int f = tid + NTH * j;                                               \
            int r = f >> 3, q = f & 7;                                           \
            uint32_t d = sbase + (uint32_t)((s) * STAGE_FLOATS + 128 * LDSS + r * LDSS + q * 4) * 4; \
            uint32_t sz = 16;                                                    \
            if (MODE == 2) sz = (colTile + r < Nn) ? 16u : 0u;                   \
            cp16(d, Bg + (size_t)(colTile + r) * K + _k0 + q * 4, sz);           \
        }                                                                        \
        cp_commit();                                                             \
    } while (0)

    ISSUE(0, 0);

    for (int it = 0; it < nIter; ++it) {
        const int s = it & 1;
        if (it + 1 < nIter) { ISSUE(it + 1, s ^ 1); cp_wait<1>(); }
        else                { cp_wait<0>(); }
        __syncthreads();

        const float* As = dyn + s * STAGE_FLOATS;
        const float* Bs = As + 128 * LDSS;
        const float* aBase = As + (warpM * 64 + g) * LDSS + t;
        const float* bBase = Bs + (warpN * 32 + g) * LDSS + t;

        #pragma unroll
        for (int kk = 0; kk < 4; kk++) {
            uint32_t af[4][4], bf[4][2];
            #pragma unroll
            for (int mt = 0; mt < 4; mt++) {
                const float* p = aBase + mt * (16 * LDSS) + kk * 8;
                float a0 = p[0], a1 = p[8 * LDSS], a2 = p[4], a3 = p[8 * LDSS + 4];
                if (MODE != 0) { a0 = to_tf32(a0); a1 = to_tf32(a1); a2 = to_tf32(a2); a3 = to_tf32(a3); }
                af[mt][0] = __float_as_uint(a0); af[mt][1] = __float_as_uint(a1);
                af[mt][2] = __float_as_uint(a2); af[mt][3] = __float_as_uint(a3);
            }
            #pragma unroll
            for (int nt = 0; nt < 4; nt++) {
                const float* p = bBase + nt * (8 * LDSS) + kk * 8;
                float b0 = p[0], b1 = p[4];
                if (MODE != 0) { b0 = to_tf32(b0); b1 = to_tf32(b1); }
                bf[nt][0] = __float_as_uint(b0); bf[nt][1] = __float_as_uint(b1);
            }
            #pragma unroll
            for (int mt = 0; mt < 4; mt++)
                #pragma unroll
                for (int nt = 0; nt < 4; nt++)
                    mma_tf32(acc[mt][nt], af[mt], bf[nt]);
        }
        __syncthreads();
    }

    // ---------------- epilogues ----------------
    if (MODE == 0) {
        #pragma unroll
        for (int mt = 0; mt < 4; mt++)
            #pragma unroll
            for (int h = 0; h < 2; h++) {
                const int R = rowTile + warpM * 64 + mt * 16 + g + h * 8;
                float* op = outp + (size_t)R * Nn;
                #pragma unroll
                for (int nt = 0; nt < 4; nt++) {
                    const int C = colTile + warpN * 32 + nt * 8 + 2 * t;
                    float2 bb = *(const float2*)(bias + C);
                    float2 o;
                    o.x = cosf(acc[mt][nt][h * 2 + 0] + bb.x) * INV_RFF_SCALAR;
                    o.y = cosf(acc[mt][nt][h * 2 + 1] + bb.y) * INV_RFF_SCALAR;
                    *(float2*)(op + C) = o;
                }
            }
    } else if (MODE == 1) {
        float* red = dyn;  // [128][4]
        #pragma unroll
        for (int mt = 0; mt < 4; mt++)
            #pragma unroll
            for (int h = 0; h < 2; h++) {
                const int lr = warpM * 64 + mt * 16 + g + h * 8;
                const float* pr = phi + (size_t)(rowTile + lr) * RFF;
                float s = 0.0f;
                #pragma unroll
                for (int nt = 0; nt < 4; nt++) {
                    const int C = colTile + warpN * 32 + nt * 8 + 2 * t;
                    float2 p = *(const float2*)(pr + C);
                    s = fmaf(acc[mt][nt][h * 2 + 0], p.x, s);
                    s = fmaf(acc[mt][nt][h * 2 + 1], p.y, s);
                }
                s += __shfl_xor_sync(0xffffffffu, s, 1);
                s += __shfl_xor_sync(0xffffffffu, s, 2);
                if (t == 0) red[lr * 4 + warpN] = s;
            }
        __syncthreads();
        if (tid < 128) {
            float s = red[tid * 4 + 0] + red[tid * 4 + 1] + red[tid * 4 + 2] + red[tid * 4 + 3];
            diagp[(size_t)blockIdx.x * NROWS + rowTile + tid] = s;
        }
    } else {
        float* scale = dyn;  // [128]
        __syncthreads();
        if (tid < 128) {
            float dg = 0.0f;
            #pragma unroll
            for (int p = 0; p < 16; p++) dg += diagp[(size_t)p * NROWS + rowTile + tid];
            scale[tid] = rsqrtf(1.0f + MFF * dg);
        }
        __syncthreads();
        #pragma unroll
        for (int mt = 0; mt < 4; mt++)
            #pragma unroll
            for (int h = 0; h < 2; h++) {
                const int lr = warpM * 64 + mt * 16 + g + h * 8;
                const int R = rowTile + lr;
                const float sc = scale[lr];
                float* op = outp + (size_t)R * OUT_F;
                #pragma unroll
                for (int nt = 0; nt < 4; nt++) {
                    const int C = colTile + warpN * 32 + nt * 8 + 2 * t;
                    if (C < OUT_F) {
                        float2 bb = *(const float2*)(bias + C);
                        float2 o;
                        o.x = (acc[mt][nt][h * 2 + 0] + bb.x) * sc;
                        o.y = (acc[mt][nt][h * 2 + 1] + bb.y) * sc;
                        *(float2*)(op + C) = o;
                    }
                }
            }
    }
    #undef ISSUE
}

// ---------------- host ----------------
extern "C" void kernel_launch(void* const* d_in, const int* in_sizes, int n_in,
                              void* d_out, int out_size)
{
    const float* D   = (const float*)d_in[0];  // [8192, 512]
    const float* W   = (const float*)d_in[1];  // [512, 2048]
    const float* b   = (const float*)d_in[2];  // [2048]
    const float* lw  = (const float*)d_in[3];  // [1000, 2048]  ([N,K])
    const float* lb  = (const float*)d_in[4];  // [1000]
    const float* cov = (const float*)d_in[5];  // [2048, 2048] symmetric ([N,K])
    float* out = (float*)d_out;                // [8192, 1000]

    float *Phi, *Abig, *Bbig, *diagp;
    cudaGetSymbolAddress((void**)&Phi,   g_Phi);
    cudaGetSymbolAddress((void**)&Abig,  g_Abig);
    cudaGetSymbolAddress((void**)&Bbig,  g_Bbig);
    cudaGetSymbolAddress((void**)&diagp, g_diag_part);

    const int smem = 2 * STAGE_FLOATS * 4;  // 73728 bytes
    cudaFuncSetAttribute(gp_mma<0>, cudaFuncAttributeMaxDynamicSharedMemorySize, smem);
    cudaFuncSetAttribute(gp_mma<1>, cudaFuncAttributeMaxDynamicSharedMemorySize, smem);
    cudaFuncSetAttribute(gp_mma<2>, cudaFuncAttributeMaxDynamicSharedMemorySize, smem);

    // prep: tf32 hi/lo split operands, K-concatenated
    split_D_k<<<(NROWS * IN_F + 255) / 256, 256>>>(D, Abig);
    split_W_k<<<dim3(RFF / 32, IN_F / 32), dim3(32, 8)>>>(W, Bbig);

    // GEMM1: Phi = cos(D@W + b)/32, split-tf32, K=1536
    gp_mma<0><<<dim3(RFF / BN, NROWS / BM), NTH, smem>>>(
        Abig, Bbig, b, Phi, nullptr, nullptr, RFF, KBIG, KBIG / BK);
    // GEMM2: diag partials from (Phi@cov) ∘ Phi, K=2048 (cov symmetric -> [N,K] direct)
    gp_mma<1><<<dim3(RFF / BN, NROWS / BM), NTH, smem>>>(
        Phi, cov, nullptr, nullptr, Phi, diagp, RFF, RFF, RFF / BK);
    // GEMM3: out = (Phi@lw^T + lb) * rsqrt(1+25*diag), K=2048, N=1000
    gp_mma<2><<<dim3((OUT_F + BN - 1) / BN, NROWS / BM), NTH, smem>>>(
        Phi, lw, lb, out, nullptr, diagp, OUT_F, RFF, RFF / BK);
}

// round 4
// speedup vs baseline: 3.1883x; 1.0706x over previous
#include <cuda_runtime.h>
#include <math.h>
#include <stdint.h>

// ---------------- problem constants ----------------
#define NROWS 8192
#define IN_F  512
#define RFF   2048
#define OUT_F 1000
#define OUT_P 1024
#define KBIG  (3*IN_F)          // 1536: [Dhi | Dlo | Dhi] x [Whi | Whi | Wlo]
#define INV_RFF_SCALAR (1.0f/32.0f)
#define MFF   25.0f

// ---------------- tiling ----------------
#define BM 128
#define BN 128
#define BK 32
#define LDSS 36                      // smem row stride in floats (padded)
#define A_FLOATS (128*LDSS)
#define STAGE_FLOATS (2*128*LDSS)    // A tile + B tile = 9216 floats
#define STAGE_BYTES (STAGE_FLOATS*4) // 36864
#define NSTAGE 3
#define NTH 256

// ---------------- device scratch (allocation-free rule) ----------------
__device__ float g_Phi[NROWS*RFF];            // 64 MB (tf32-rounded values)
__device__ float g_Abig[NROWS*KBIG];          // 48 MB
__device__ float g_Bbig[RFF*KBIG];            // 12 MB  ([N][K])
__device__ float g_covt[RFF*RFF];             // 16 MB  tf32-rounded cov
__device__ float g_lwt[OUT_P*RFF];            // 8  MB  tf32-rounded logit_w, zero-padded
__device__ float g_diag_part[16*NROWS];

// ---------------- helpers ----------------
__device__ __forceinline__ uint32_t smem_u32(const void* p) {
    uint32_t r;
    asm("{ .reg .u64 t; cvta.to.shared.u64 t, %1; cvt.u32.u64 %0, t; }" : "=r"(r) : "l"(p));
    return r;
}
__device__ __forceinline__ float to_tf32(float x) {
    float r; asm("cvt.rna.tf32.f32 %0, %1;" : "=f"(r) : "f"(x)); return r;
}
__device__ __forceinline__ void cp16(uint32_t d, const void* s) {
    asm volatile("cp.async.cg.shared.global [%0], [%1], 16;" :: "r"(d), "l"(s));
}
__device__ __forceinline__ void cp_commit() { asm volatile("cp.async.commit_group;"); }
template <int N> __device__ __forceinline__ void cp_wait() {
    asm volatile("cp.async.wait_group %0;" :: "n"(N));
}
__device__ __forceinline__ void ldsm_x4(uint32_t* r, uint32_t a) {
    asm volatile("ldmatrix.sync.aligned.m8n8.x4.shared.b16 {%0,%1,%2,%3}, [%4];"
        : "=r"(r[0]), "=r"(r[1]), "=r"(r[2]), "=r"(r[3]) : "r"(a));
}
__device__ __forceinline__ void ldsm_x2(uint32_t* r, uint32_t a) {
    asm volatile("ldmatrix.sync.aligned.m8n8.x2.shared.b16 {%0,%1}, [%2];"
        : "=r"(r[0]), "=r"(r[1]) : "r"(a));
}
__device__ __forceinline__ void mma_tf32(float* c, const uint32_t* a, const uint32_t* b) {
    asm volatile(
        "mma.sync.aligned.m16n8k8.row.col.f32.tf32.tf32.f32 "
        "{%0,%1,%2,%3}, {%4,%5,%6,%7}, {%8,%9}, {%0,%1,%2,%3};"
        : "+f"(c[0]), "+f"(c[1]), "+f"(c[2]), "+f"(c[3])
        : "r"(a[0]), "r"(a[1]), "r"(a[2]), "r"(a[3]), "r"(b[0]), "r"(b[1]));
}

// ---------------- prep kernels ----------------
__global__ void split_D_k(const float* __restrict__ D, float* __restrict__ A) {
    int idx = blockIdx.x * blockDim.x + threadIdx.x;
    if (idx >= NROWS * IN_F) return;
    int r = idx >> 9, k = idx & (IN_F - 1);
    float x = D[idx], hi = to_tf32(x), lo = x - hi;
    float* p = A + (size_t)r * KBIG;
    p[k] = hi; p[IN_F + k] = to_tf32(lo); p[2 * IN_F + k] = hi;
}

__global__ void split_W_k(const float* __restrict__ W, float* __restrict__ Bb) {
    __shared__ float t[32][33];
    int nb = blockIdx.x * 32, kb = blockIdx.y * 32;
    int tx = threadIdx.x, ty0 = threadIdx.y;
    #pragma unroll
    for (int i = 0; i < 32; i += 8) {
        int ty = ty0 + i;
        t[ty][tx] = W[(size_t)(kb + ty) * RFF + nb + tx];
    }
    __syncthreads();
    #pragma unroll
    for (int i = 0; i < 32; i += 8) {
        int ty = ty0 + i;
        int n = nb + ty, k = kb + tx;
        float x = t[tx][ty], hi = to_tf32(x), lo = x - hi;
        float* p = Bb + (size_t)n * KBIG;
        p[k] = hi; p[IN_F + k] = hi; p[2 * IN_F + k] = to_tf32(lo);
    }
}

__global__ void cvt_cov(const float* __restrict__ c, float* __restrict__ o) {
    int idx = blockIdx.x * blockDim.x + threadIdx.x;
    if (idx < RFF * RFF) o[idx] = to_tf32(c[idx]);
}
__global__ void cvt_lw(const float* __restrict__ lw, float* __restrict__ o) {
    int idx = blockIdx.x * blockDim.x + threadIdx.x;
    if (idx >= OUT_P * RFF) return;
    int n = idx / RFF;
    o[idx] = (n < OUT_F) ? to_tf32(lw[idx]) : 0.0f;
}

// ---------------- main mma.sync GEMM ----------------
// A [M,K] row-major, B [N,K] row-major, all values tf32-exact.
// MODE 0: Phi = tf32(cos(acc + bias)/32)
// MODE 1: diag partial = rowsum(acc * Phi)
// MODE 2: out = (acc + lb) * rsqrt(1 + 25*diag)
template <int MODE>
__global__ void __launch_bounds__(NTH, 2)
gp_mma(const float* __restrict__ Ag, const float* __restrict__ Bg,
       const float* __restrict__ bias, float* __restrict__ outp,
       const float* __restrict__ phi, float* __restrict__ diagp,
       int Nn, int K, int nIter)
{
    extern __shared__ float dyn[];
    const int tid = threadIdx.x;
    const int wid = tid >> 5, lane = tid & 31;
    const int g = lane >> 2, t = lane & 3;
    const int warpM = wid >> 2, warpN = wid & 3;  // 2x4 warp grid, 64x32 warp tiles
    const int rowTile = blockIdx.y * BM, colTile = blockIdx.x * BN;
    const uint32_t sbase = smem_u32(dyn);

    // ldmatrix per-lane byte offsets within a stage
    const uint32_t aLdOff = (uint32_t)(((warpM * 64 + ((lane >> 3) & 1) * 8 + (lane & 7)) * LDSS
                                        + ((lane >> 4) & 1) * 4) * 4);
    const uint32_t bLdOff = (uint32_t)(A_FLOATS * 4
                                        + ((warpN * 32 + (lane & 7)) * LDSS
                                        + ((lane >> 3) & 1) * 4) * 4);

    float acc[4][4][4];
    #pragma unroll
    for (int mt = 0; mt < 4; mt++)
        #pragma unroll
        for (int nt = 0; nt < 4; nt++)
            #pragma unroll
            for (int r = 0; r < 4; r++) acc[mt][nt][r] = 0.0f;

    #define ISSUE(it, s) do {                                                     \
        const int _k0 = (it) * BK;                                                \
        _Pragma("unroll")                                                         \
        for (int j = 0; j < 4; j++) {                                             \
            int f = tid + NTH * j;                                                \
            int r = f >> 3, q = f & 7;                                            \
            uint32_t d = sbase + (uint32_t)(s) * STAGE_BYTES + (uint32_t)(r * LDSS + q * 4) * 4; \
            cp16(d, Ag + (size_t)(rowTile + r) * K + _k0 + q * 4);                \
        }                                                                         \
        _Pragma("unroll")                                                         \
        for (int j = 0; j < 4; j++) {                                             \
            int f = tid + NTH * j;                                                \
            int r = f >> 3, q = f & 7;                                            \
            uint32_t d = sbase + (uint32_t)(s) * STAGE_BYTES + (uint32_t)(A_FLOATS + r * LDSS + q * 4) * 4; \
            cp16(d, Bg + (size_t)(colTile + r) * K + _k0 + q * 4);                \
        }                                                                         \
        cp_commit();                                                              \
    } while (0)

    ISSUE(0, 0);
    if (nIter > 1) ISSUE(1, 1);

    int s = 0;
    for (int it = 0; it < nIter; ++it) {
        if (it + 2 < nIter) { ISSUE(it + 2, (s + 2) % NSTAGE); cp_wait<2>(); }
        else if (it + 1 < nIter) cp_wait<1>();
        else cp_wait<0>();
        __syncthreads();

        const uint32_t stageB = sbase + (uint32_t)s * STAGE_BYTES;
        const uint32_t aB = stageB + aLdOff;
        const uint32_t bB = stageB + bLdOff;

        #pragma unroll
        for (int kk = 0; kk < 4; kk++) {
            uint32_t af[4][4], bf[4][2];
            #pragma unroll
            for (int mt = 0; mt < 4; mt++)
                ldsm_x4(af[mt], aB + (uint32_t)((mt * 16 * LDSS + kk * 8) * 4));
            #pragma unroll
            for (int nt = 0; nt < 4; nt++)
                ldsm_x2(bf[nt], bB + (uint32_t)((nt * 8 * LDSS + kk * 8) * 4));
            #pragma unroll
            for (int mt = 0; mt < 4; mt++)
                #pragma unroll
                for (int nt = 0; nt < 4; nt++)
                    mma_tf32(acc[mt][nt], af[mt], bf[nt]);
        }
        __syncthreads();
        s = (s + 1 == NSTAGE) ? 0 : s + 1;
    }

    // ---------------- epilogues ----------------
    if (MODE == 0) {
        #pragma unroll
        for (int mt = 0; mt < 4; mt++)
            #pragma unroll
            for (int h = 0; h < 2; h++) {
                const int R = rowTile + warpM * 64 + mt * 16 + g + h * 8;
                float* op = outp + (size_t)R * Nn;
                #pragma unroll
                for (int nt = 0; nt < 4; nt++) {
                    const int C = colTile + warpN * 32 + nt * 8 + 2 * t;
                    float2 bb = *(const float2*)(bias + C);
                    float2 o;
                    o.x = to_tf32(cosf(acc[mt][nt][h * 2 + 0] + bb.x) * INV_RFF_SCALAR);
                    o.y = to_tf32(cosf(acc[mt][nt][h * 2 + 1] + bb.y) * INV_RFF_SCALAR);
                    *(float2*)(op + C) = o;
                }
            }
    } else if (MODE == 1) {
        float* red = dyn;  // [128][4]
        #pragma unroll
        for (int mt = 0; mt < 4; mt++)
            #pragma unroll
            for (int h = 0; h < 2; h++) {
                const int lr = warpM * 64 + mt * 16 + g + h * 8;
                const float* pr = phi + (size_t)(rowTile + lr) * RFF;
                float sum = 0.0f;
                #pragma unroll
                for (int nt = 0; nt < 4; nt++) {
                    const int C = colTile + warpN * 32 + nt * 8 + 2 * t;
                    float2 p = *(const float2*)(pr + C);
                    sum = fmaf(acc[mt][nt][h * 2 + 0], p.x, sum);
                    sum = fmaf(acc[mt][nt][h * 2 + 1], p.y, sum);
                }
                sum += __shfl_xor_sync(0xffffffffu, sum, 1);
                sum += __shfl_xor_sync(0xffffffffu, sum, 2);
                if (t == 0) red[lr * 4 + warpN] = sum;
            }
        __syncthreads();
        if (tid < 128) {
            float sum = red[tid * 4 + 0] + red[tid * 4 + 1] + red[tid * 4 + 2] + red[tid * 4 + 3];
            diagp[(size_t)blockIdx.x * NROWS + rowTile + tid] = sum;
        }
    } else {
        float* scale = dyn;  // [128]
        __syncthreads();
        if (tid < 128) {
            float dg = 0.0f;
            #pragma unroll
            for (int p = 0; p < 16; p++) dg += diagp[(size_t)p * NROWS + rowTile + tid];
            scale[tid] = rsqrtf(1.0f + MFF * dg);
        }
        __syncthreads();
        #pragma unroll
        for (int mt = 0; mt < 4; mt++)
            #pragma unroll
            for (int h = 0; h < 2; h++) {
                const int lr = warpM * 64 + mt * 16 + g + h * 8;
                const int R = rowTile + lr;
                const float sc = scale[lr];
                float* op = outp + (size_t)R * OUT_F;
                #pragma unroll
                for (int nt = 0; nt < 4; nt++) {
                    const int C = colTile + warpN * 32 + nt * 8 + 2 * t;
                    if (C < OUT_F) {
                        float2 bb = *(const float2*)(bias + C);
                        float2 o;
                        o.x = (acc[mt][nt][h * 2 + 0] + bb.x) * sc;
                        o.y = (acc[mt][nt][h * 2 + 1] + bb.y) * sc;
                        *(float2*)(op + C) = o;
                    }
                }
            }
    }
    #undef ISSUE
}

// ---------------- host ----------------
extern "C" void kernel_launch(void* const* d_in, const int* in_sizes, int n_in,
                              void* d_out, int out_size)
{
    const float* D   = (const float*)d_in[0];  // [8192, 512]
    const float* W   = (const float*)d_in[1];  // [512, 2048]
    const float* b   = (const float*)d_in[2];  // [2048]
    const float* lw  = (const float*)d_in[3];  // [1000, 2048]
    const float* lb  = (const float*)d_in[4];  // [1000]
    const float* cov = (const float*)d_in[5];  // [2048, 2048] symmetric
    float* out = (float*)d_out;                // [8192, 1000]

    float *Phi, *Abig, *Bbig, *covt, *lwt, *diagp;
    cudaGetSymbolAddress((void**)&Phi,   g_Phi);
    cudaGetSymbolAddress((void**)&Abig,  g_Abig);
    cudaGetSymbolAddress((void**)&Bbig,  g_Bbig);
    cudaGetSymbolAddress((void**)&covt,  g_covt);
    cudaGetSymbolAddress((void**)&lwt,   g_lwt);
    cudaGetSymbolAddress((void**)&diagp, g_diag_part);

    const int smem = NSTAGE * STAGE_BYTES;  // 110592 bytes
    cudaFuncSetAttribute(gp_mma<0>, cudaFuncAttributeMaxDynamicSharedMemorySize, smem);
    cudaFuncSetAttribute(gp_mma<1>, cudaFuncAttributeMaxDynamicSharedMemorySize, smem);
    cudaFuncSetAttribute(gp_mma<2>, cudaFuncAttributeMaxDynamicSharedMemorySize, smem);

    // prep
    split_D_k<<<(NROWS * IN_F + 255) / 256, 256>>>(D, Abig);
    split_W_k<<<dim3(RFF / 32, IN_F / 32), dim3(32, 8)>>>(W, Bbig);
    cvt_cov<<<(RFF * RFF + 255) / 256, 256>>>(cov, covt);
    cvt_lw<<<(OUT_P * RFF + 255) / 256, 256>>>(lw, lwt);

    // GEMM1: Phi = tf32(cos(D@W + b)/32), split-tf32, K=1536
    gp_mma<0><<<dim3(RFF / BN, NROWS / BM), NTH, smem>>>(
        Abig, Bbig, b, Phi, nullptr, nullptr, RFF, KBIG, KBIG / BK);
    // GEMM2: diag partials from (Phi@cov) ∘ Phi, K=2048
    gp_mma<1><<<dim3(RFF / BN, NROWS / BM), NTH, smem>>>(
        Phi, covt, nullptr, nullptr, Phi, diagp, RFF, RFF, RFF / BK);
    // GEMM3: out = (Phi@lw^T + lb) * rsqrt(1+25*diag), K=2048, N padded to 1024
    gp_mma<2><<<dim3(OUT_P / BN, NROWS / BM), NTH, smem>>>(
        Phi, lwt, lb, out, nullptr, diagp, OUT_F, RFF, RFF / BK);
}

// round 5
// speedup vs baseline: 3.6981x; 1.1599x over previous
#include <cuda_runtime.h>
#include <math.h>
#include <stdint.h>

// ---------------- problem constants ----------------
#define NROWS 8192
#define IN_F  512
#define RFF   2048
#define OUT_F 1000
#define OUT_P 1024
#define KBIG  (3*IN_F)          // 1536: [Dhi | Dlo | Dhi] x [Whi | Whi | Wlo]
#define INV_RFF_SCALAR (1.0f/32.0f)
#define MFF   25.0f

// ---------------- tiling ----------------
#define BM 128
#define BN 128
#define BK 32
#define LDSS 36                      // smem row stride in floats (padded)
#define A_FLOATS (128*LDSS)
#define STAGE_FLOATS (2*128*LDSS)
#define STAGE_BYTES (STAGE_FLOATS*4) // 36864
#define NSTAGE 3
#define NTH 256

// ---------------- device scratch ----------------
__device__ float g_Phi[NROWS*RFF];            // 64 MB (tf32-rounded)
__device__ float g_Abig[NROWS*KBIG];          // 48 MB
__device__ float g_Bbig[RFF*KBIG];            // 12 MB  ([N][K])
__device__ float g_covt[RFF*RFF];             // 16 MB  tf32(cov)
__device__ float g_covt2[RFF*RFF];            // 16 MB  tf32(2*cov)
__device__ float g_lwt[OUT_P*RFF];            // 8  MB  tf32(logit_w), zero-padded
__device__ float g_diag_part[16*NROWS];

// ---------------- helpers ----------------
__device__ __forceinline__ uint32_t smem_u32(const void* p) {
    uint32_t r;
    asm("{ .reg .u64 t; cvta.to.shared.u64 t, %1; cvt.u32.u64 %0, t; }" : "=r"(r) : "l"(p));
    return r;
}
__device__ __forceinline__ float to_tf32(float x) {
    float r; asm("cvt.rna.tf32.f32 %0, %1;" : "=f"(r) : "f"(x)); return r;
}
__device__ __forceinline__ void cp16(uint32_t d, const void* s) {
    asm volatile("cp.async.cg.shared.global [%0], [%1], 16;" :: "r"(d), "l"(s));
}
__device__ __forceinline__ void cp_commit() { asm volatile("cp.async.commit_group;"); }
template <int N> __device__ __forceinline__ void cp_wait() {
    asm volatile("cp.async.wait_group %0;" :: "n"(N));
}
__device__ __forceinline__ void ldsm_x4(uint32_t* r, uint32_t a) {
    asm volatile("ldmatrix.sync.aligned.m8n8.x4.shared.b16 {%0,%1,%2,%3}, [%4];"
        : "=r"(r[0]), "=r"(r[1]), "=r"(r[2]), "=r"(r[3]) : "r"(a));
}
__device__ __forceinline__ void ldsm_x2(uint32_t* r, uint32_t a) {
    asm volatile("ldmatrix.sync.aligned.m8n8.x2.shared.b16 {%0,%1}, [%2];"
        : "=r"(r[0]), "=r"(r[1]) : "r"(a));
}
__device__ __forceinline__ void mma_tf32(float* c, const uint32_t* a, const uint32_t* b) {
    asm volatile(
        "mma.sync.aligned.m16n8k8.row.col.f32.tf32.tf32.f32 "
        "{%0,%1,%2,%3}, {%4,%5,%6,%7}, {%8,%9}, {%0,%1,%2,%3};"
        : "+f"(c[0]), "+f"(c[1]), "+f"(c[2]), "+f"(c[3])
        : "r"(a[0]), "r"(a[1]), "r"(a[2]), "r"(a[3]), "r"(b[0]), "r"(b[1]));
}

// ---------------- prep kernels ----------------
__global__ void split_D_k(const float* __restrict__ D, float* __restrict__ A) {
    int idx = blockIdx.x * blockDim.x + threadIdx.x;
    if (idx >= NROWS * IN_F) return;
    int r = idx >> 9, k = idx & (IN_F - 1);
    float x = D[idx], hi = to_tf32(x), lo = x - hi;
    float* p = A + (size_t)r * KBIG;
    p[k] = hi; p[IN_F + k] = to_tf32(lo); p[2 * IN_F + k] = hi;
}

__global__ void split_W_k(const float* __restrict__ W, float* __restrict__ Bb) {
    __shared__ float t[32][33];
    int nb = blockIdx.x * 32, kb = blockIdx.y * 32;
    int tx = threadIdx.x, ty0 = threadIdx.y;
    #pragma unroll
    for (int i = 0; i < 32; i += 8) {
        int ty = ty0 + i;
        t[ty][tx] = W[(size_t)(kb + ty) * RFF + nb + tx];
    }
    __syncthreads();
    #pragma unroll
    for (int i = 0; i < 32; i += 8) {
        int ty = ty0 + i;
        int n = nb + ty, k = kb + tx;
        float x = t[tx][ty], hi = to_tf32(x), lo = x - hi;
        float* p = Bb + (size_t)n * KBIG;
        p[k] = hi; p[IN_F + k] = hi; p[2 * IN_F + k] = to_tf32(lo);
    }
}

__global__ void cvt_cov(const float* __restrict__ c, float* __restrict__ o1, float* __restrict__ o2) {
    int idx = blockIdx.x * blockDim.x + threadIdx.x;
    if (idx < RFF * RFF) {
        float v = to_tf32(c[idx]);
        o1[idx] = v;
        o2[idx] = 2.0f * v;   // exact (exponent bump)
    }
}
__global__ void cvt_lw(const float* __restrict__ lw, float* __restrict__ o) {
    int idx = blockIdx.x * blockDim.x + threadIdx.x;
    if (idx >= OUT_P * RFF) return;
    int n = idx / RFF;
    o[idx] = (n < OUT_F) ? to_tf32(lw[idx]) : 0.0f;
}

// ---------------- main mma.sync GEMM ----------------
// A [M,K] rm, B [N,K] rm, all values tf32-exact.
// MODE 0: Phi = tf32(cos(acc + bias)/32)
// MODE 1: diag partial = rowsum(acc * Phi); triangular K using Bg2=2*cov off-diag
// MODE 2: out = (acc + lb) * rsqrt(1 + 25*diag)
template <int MODE>
__global__ void __launch_bounds__(NTH, 2)
gp_mma(const float* __restrict__ Ag, const float* __restrict__ Bg,
       const float* __restrict__ Bg2,
       const float* __restrict__ bias, float* __restrict__ outp,
       const float* __restrict__ phi, float* __restrict__ diagp,
       int Nn, int K, int nIterIn)
{
    extern __shared__ float dyn[];
    const int tid = threadIdx.x;
    const int wid = tid >> 5, lane = tid & 31;
    const int g = lane >> 2, t = lane & 3;
    const int warpM = wid >> 2, warpN = wid & 3;  // 2x4 warp grid, 64x32 warp tiles
    // MODE 1: reversed col-block order so the longest (triangular) blocks start first
    const int cblk = (MODE == 1) ? (gridDim.x - 1 - blockIdx.x) : blockIdx.x;
    const int rowTile = blockIdx.y * BM, colTile = cblk * BN;
    // MODE 1: triangular K — only k-blocks <= this col-block
    const int nIter = (MODE == 1) ? ((colTile + BN) / BK) : nIterIn;
    const uint32_t sbase = smem_u32(dyn);

    const uint32_t aLdOff = (uint32_t)(((warpM * 64 + ((lane >> 3) & 1) * 8 + (lane & 7)) * LDSS
                                        + ((lane >> 4) & 1) * 4) * 4);
    const uint32_t bLdOff = (uint32_t)(A_FLOATS * 4
                                        + ((warpN * 32 + (lane & 7)) * LDSS
                                        + ((lane >> 3) & 1) * 4) * 4);

    float acc[4][4][4];
    #pragma unroll
    for (int mt = 0; mt < 4; mt++)
        #pragma unroll
        for (int nt = 0; nt < 4; nt++)
            #pragma unroll
            for (int r = 0; r < 4; r++) acc[mt][nt][r] = 0.0f;

    #define ISSUE(it, s) do {                                                     \
        const int _k0 = (it) * BK;                                                \
        const float* _bs = (MODE == 1 && _k0 < colTile) ? Bg2 : Bg;               \
        _Pragma("unroll")                                                         \
        for (int j = 0; j < 4; j++) {                                             \
            int f = tid + NTH * j;                                                \
            int r = f >> 3, q = f & 7;                                            \
            uint32_t d = sbase + (uint32_t)(s) * STAGE_BYTES + (uint32_t)(r * LDSS + q * 4) * 4; \
            cp16(d, Ag + (size_t)(rowTile + r) * K + _k0 + q * 4);                \
        }                                                                         \
        _Pragma("unroll")                                                         \
        for (int j = 0; j < 4; j++) {                                             \
            int f = tid + NTH * j;                                                \
            int r = f >> 3, q = f & 7;                                            \
            uint32_t d = sbase + (uint32_t)(s) * STAGE_BYTES + (uint32_t)(A_FLOATS + r * LDSS + q * 4) * 4; \
            cp16(d, _bs + (size_t)(colTile + r) * K + _k0 + q * 4);               \
        }                                                                         \
        cp_commit();                                                              \
    } while (0)

    ISSUE(0, 0);
    if (nIter > 1) ISSUE(1, 1);

    int s = 0;
    for (int it = 0; it < nIter; ++it) {
        if (it + 2 < nIter) { ISSUE(it + 2, (s + 2) % NSTAGE); cp_wait<2>(); }
        else if (it + 1 < nIter) cp_wait<1>();
        else cp_wait<0>();
        __syncthreads();

        const uint32_t stageB = sbase + (uint32_t)s * STAGE_BYTES;
        const uint32_t aB = stageB + aLdOff;
        const uint32_t bB = stageB + bLdOff;

        #pragma unroll
        for (int kk = 0; kk < 4; kk++) {
            uint32_t af[4][4], bf[4][2];
            #pragma unroll
            for (int mt = 0; mt < 4; mt++)
                ldsm_x4(af[mt], aB + (uint32_t)((mt * 16 * LDSS + kk * 8) * 4));
            #pragma unroll
            for (int nt = 0; nt < 4; nt++)
                ldsm_x2(bf[nt], bB + (uint32_t)((nt * 8 * LDSS + kk * 8) * 4));
            #pragma unroll
            for (int mt = 0; mt < 4; mt++)
                #pragma unroll
                for (int nt = 0; nt < 4; nt++)
                    mma_tf32(acc[mt][nt], af[mt], bf[nt]);
        }
        __syncthreads();
        s = (s + 1 == NSTAGE) ? 0 : s + 1;
    }

    // ---------------- epilogues ----------------
    if (MODE == 0) {
        #pragma unroll
        for (int mt = 0; mt < 4; mt++)
            #pragma unroll
            for (int h = 0; h < 2; h++) {
                const int R = rowTile + warpM * 64 + mt * 16 + g + h * 8;
                float* op = outp + (size_t)R * Nn;
                #pragma unroll
                for (int nt = 0; nt < 4; nt++) {
                    const int C = colTile + warpN * 32 + nt * 8 + 2 * t;
                    float2 bb = *(const float2*)(bias + C);
                    float2 o;
                    o.x = to_tf32(cosf(acc[mt][nt][h * 2 + 0] + bb.x) * INV_RFF_SCALAR);
                    o.y = to_tf32(cosf(acc[mt][nt][h * 2 + 1] + bb.y) * INV_RFF_SCALAR);
                    *(float2*)(op + C) = o;
                }
            }
    } else if (MODE == 1) {
        float* red = dyn;  // [128][4]
        #pragma unroll
        for (int mt = 0; mt < 4; mt++)
            #pragma unroll
            for (int h = 0; h < 2; h++) {
                const int lr = warpM * 64 + mt * 16 + g + h * 8;
                const float* pr = phi + (size_t)(rowTile + lr) * RFF;
                float sum = 0.0f;
                #pragma unroll
                for (int nt = 0; nt < 4; nt++) {
                    const int C = colTile + warpN * 32 + nt * 8 + 2 * t;
                    float2 p = *(const float2*)(pr + C);
                    sum = fmaf(acc[mt][nt][h * 2 + 0], p.x, sum);
                    sum = fmaf(acc[mt][nt][h * 2 + 1], p.y, sum);
                }
                sum += __shfl_xor_sync(0xffffffffu, sum, 1);
                sum += __shfl_xor_sync(0xffffffffu, sum, 2);
                if (t == 0) red[lr * 4 + warpN] = sum;
            }
        __syncthreads();
        if (tid < 128) {
            float sum = red[tid * 4 + 0] + red[tid * 4 + 1] + red[tid * 4 + 2] + red[tid * 4 + 3];
            diagp[(size_t)cblk * NROWS + rowTile + tid] = sum;
        }
    } else {
        float* scale = dyn;  // [128]
        __syncthreads();
        if (tid < 128) {
            float dg = 0.0f;
            #pragma unroll
            for (int p = 0; p < 16; p++) dg += diagp[(size_t)p * NROWS + rowTile + tid];
            scale[tid] = rsqrtf(1.0f + MFF * dg);
        }
        __syncthreads();
        #pragma unroll
        for (int mt = 0; mt < 4; mt++)
            #pragma unroll
            for (int h = 0; h < 2; h++) {
                const int lr = warpM * 64 + mt * 16 + g + h * 8;
                const int R = rowTile + lr;
                const float sc = scale[lr];
                float* op = outp + (size_t)R * OUT_F;
                #pragma unroll
                for (int nt = 0; nt < 4; nt++) {
                    const int C = colTile + warpN * 32 + nt * 8 + 2 * t;
                    if (C < OUT_F) {
                        float2 bb = *(const float2*)(bias + C);
                        float2 o;
                        o.x = (acc[mt][nt][h * 2 + 0] + bb.x) * sc;
                        o.y = (acc[mt][nt][h * 2 + 1] + bb.y) * sc;
                        *(float2*)(op + C) = o;
                    }
                }
            }
    }
    #undef ISSUE
}

// ---------------- host ----------------
extern "C" void kernel_launch(void* const* d_in, const int* in_sizes, int n_in,
                              void* d_out, int out_size)
{
    const float* D   = (const float*)d_in[0];
    const float* W   = (const float*)d_in[1];
    const float* b   = (const float*)d_in[2];
    const float* lw  = (const float*)d_in[3];
    const float* lb  = (const float*)d_in[4];
    const float* cov = (const float*)d_in[5];
    float* out = (float*)d_out;

    float *Phi, *Abig, *Bbig, *covt, *covt2, *lwt, *diagp;
    cudaGetSymbolAddress((void**)&Phi,   g_Phi);
    cudaGetSymbolAddress((void**)&Abig,  g_Abig);
    cudaGetSymbolAddress((void**)&Bbig,  g_Bbig);
    cudaGetSymbolAddress((void**)&covt,  g_covt);
    cudaGetSymbolAddress((void**)&covt2, g_covt2);
    cudaGetSymbolAddress((void**)&lwt,   g_lwt);
    cudaGetSymbolAddress((void**)&diagp, g_diag_part);

    const int smem = NSTAGE * STAGE_BYTES;  // 110592 bytes
    cudaFuncSetAttribute(gp_mma<0>, cudaFuncAttributeMaxDynamicSharedMemorySize, smem);
    cudaFuncSetAttribute(gp_mma<1>, cudaFuncAttributeMaxDynamicSharedMemorySize, smem);
    cudaFuncSetAttribute(gp_mma<2>, cudaFuncAttributeMaxDynamicSharedMemorySize, smem);

    // prep
    split_D_k<<<(NROWS * IN_F + 255) / 256, 256>>>(D, Abig);
    split_W_k<<<dim3(RFF / 32, IN_F / 32), dim3(32, 8)>>>(W, Bbig);
    cvt_cov<<<(RFF * RFF + 255) / 256, 256>>>(cov, covt, covt2);
    cvt_lw<<<(OUT_P * RFF + 255) / 256, 256>>>(lw, lwt);

    // GEMM1: Phi = tf32(cos(D@W + b)/32), split-tf32, K=1536
    gp_mma<0><<<dim3(RFF / BN, NROWS / BM), NTH, smem>>>(
        Abig, Bbig, nullptr, b, Phi, nullptr, nullptr, RFF, KBIG, KBIG / BK);
    // GEMM2: triangular diag partials, K limited per col-block (cov symmetric)
    gp_mma<1><<<dim3(RFF / BN, NROWS / BM), NTH, smem>>>(
        Phi, covt, covt2, nullptr, nullptr, Phi, diagp, RFF, RFF, 0);
    // GEMM3: out = (Phi@lw^T + lb) * rsqrt(1+25*diag), K=2048, N padded to 1024
    gp_mma<2><<<dim3(OUT_P / BN, NROWS / BM), NTH, smem>>>(
        Phi, lwt, nullptr, lb, out, nullptr, diagp, OUT_F, RFF, RFF / BK);
}

// round 6
// speedup vs baseline: 3.9852x; 1.0776x over previous
#include <cuda_runtime.h>
#include <math.h>
#include <stdint.h>

// ---------------- problem constants ----------------
#define NROWS 8192
#define IN_F  512
#define RFF   2048
#define OUT_F 1000
#define KBIG  (3*IN_F)          // 1536: [Dhi | Dlo | Dhi] x [Whi | Whi | Wlo]
#define INV_RFF_SCALAR (1.0f/32.0f)
#define MFF   25.0f

// ---------------- tiling ----------------
#define BM 128
#define BN 128
#define BK 32
#define LDSS 36
#define A_FLOATS (128*LDSS)
#define STAGE_FLOATS (2*128*LDSS)
#define STAGE_BYTES (STAGE_FLOATS*4) // 36864
#define NSTAGE 3
#define NTH 256
#define GRID_P 296                   // persistent grid: 2 CTAs x 148 SMs

// ---------------- device scratch ----------------
__device__ float g_Phi[NROWS*RFF];            // 64 MB tf32(Phi)
__device__ float g_Phi2[NROWS*RFF];           // 64 MB 2*tf32(Phi) (exact)
__device__ float g_Abig[NROWS*KBIG];          // 48 MB
__device__ float g_Bbig[RFF*KBIG];            // 12 MB ([N][K])
__device__ float g_diag_part[16*NROWS];
__device__ int   g_ctr[4];

// ---------------- helpers ----------------
__device__ __forceinline__ uint32_t smem_u32(const void* p) {
    uint32_t r;
    asm("{ .reg .u64 t; cvta.to.shared.u64 t, %1; cvt.u32.u64 %0, t; }" : "=r"(r) : "l"(p));
    return r;
}
__device__ __forceinline__ float to_tf32(float x) {
    float r; asm("cvt.rna.tf32.f32 %0, %1;" : "=f"(r) : "f"(x)); return r;
}
__device__ __forceinline__ void cp16(uint32_t d, const void* s) {
    asm volatile("cp.async.cg.shared.global [%0], [%1], 16;" :: "r"(d), "l"(s));
}
__device__ __forceinline__ void cp16z(uint32_t d, const void* s, uint32_t sz) {
    asm volatile("cp.async.cg.shared.global [%0], [%1], 16, %2;" :: "r"(d), "l"(s), "r"(sz));
}
__device__ __forceinline__ void cp_commit() { asm volatile("cp.async.commit_group;"); }
template <int N> __device__ __forceinline__ void cp_wait() {
    asm volatile("cp.async.wait_group %0;" :: "n"(N));
}
__device__ __forceinline__ void ldsm_x4(uint32_t* r, uint32_t a) {
    asm volatile("ldmatrix.sync.aligned.m8n8.x4.shared.b16 {%0,%1,%2,%3}, [%4];"
        : "=r"(r[0]), "=r"(r[1]), "=r"(r[2]), "=r"(r[3]) : "r"(a));
}
__device__ __forceinline__ void ldsm_x2(uint32_t* r, uint32_t a) {
    asm volatile("ldmatrix.sync.aligned.m8n8.x2.shared.b16 {%0,%1}, [%2];"
        : "=r"(r[0]), "=r"(r[1]) : "r"(a));
}
__device__ __forceinline__ void mma_tf32(float* c, const uint32_t* a, const uint32_t* b) {
    asm volatile(
        "mma.sync.aligned.m16n8k8.row.col.f32.tf32.tf32.f32 "
        "{%0,%1,%2,%3}, {%4,%5,%6,%7}, {%8,%9}, {%0,%1,%2,%3};"
        : "+f"(c[0]), "+f"(c[1]), "+f"(c[2]), "+f"(c[3])
        : "r"(a[0]), "r"(a[1]), "r"(a[2]), "r"(a[3]), "r"(b[0]), "r"(b[1]));
}

// ---------------- prep kernels ----------------
__global__ void split_D_k(const float* __restrict__ D, float* __restrict__ A) {
    int idx = blockIdx.x * blockDim.x + threadIdx.x;
    if (idx >= NROWS * IN_F) return;
    int r = idx >> 9, k = idx & (IN_F - 1);
    float x = D[idx], hi = to_tf32(x), lo = x - hi;
    float* p = A + (size_t)r * KBIG;
    p[k] = hi; p[IN_F + k] = to_tf32(lo); p[2 * IN_F + k] = hi;
}

__global__ void split_W_k(const float* __restrict__ W, float* __restrict__ Bb) {
    __shared__ float t[32][33];
    int nb = blockIdx.x * 32, kb = blockIdx.y * 32;
    int tx = threadIdx.x, ty0 = threadIdx.y;
    #pragma unroll
    for (int i = 0; i < 32; i += 8) {
        int ty = ty0 + i;
        t[ty][tx] = W[(size_t)(kb + ty) * RFF + nb + tx];
    }
    __syncthreads();
    #pragma unroll
    for (int i = 0; i < 32; i += 8) {
        int ty = ty0 + i;
        int n = nb + ty, k = kb + tx;
        float x = t[tx][ty], hi = to_tf32(x), lo = x - hi;
        float* p = Bb + (size_t)n * KBIG;
        p[k] = hi; p[IN_F + k] = hi; p[2 * IN_F + k] = to_tf32(lo);
    }
}

// ---------------- persistent mma.sync GEMM ----------------
// MODE 0: Phi = tf32(cos(acc+bias)/32), also writes Phi2 = 2*Phi
//         A=g_Abig [M,KBIG], B=g_Bbig [N,KBIG], nTiles=16x64
// MODE 1: diag partial = rowsum(acc*Phi); triangular K; A = Phi2 (k<colTile) else Phi;
//         B = raw cov (RZ-truncated by HMMA); tiles LPT-ordered (long jb first)
// MODE 2: out = (acc+lb)*rsqrt(1+25*diag); B = raw logit_w, zero-filled rows >= 1000
template <int MODE>
__global__ void __launch_bounds__(NTH, 2)
gp_mma(const float* __restrict__ Ag, const float* __restrict__ Ag2,
       const float* __restrict__ Bg,
       const float* __restrict__ bias, float* __restrict__ outp,
       float* __restrict__ outp2,
       const float* __restrict__ phi, float* __restrict__ diagp,
       int* __restrict__ ctr, int nTiles, int K, int nIterFix)
{
    extern __shared__ float dyn[];
    __shared__ int s_tile;
    const int tid = threadIdx.x;
    const int wid = tid >> 5, lane = tid & 31;
    const int g = lane >> 2, t = lane & 3;
    const int warpM = wid >> 2, warpN = wid & 3;
    const uint32_t sbase = smem_u32(dyn);

    const uint32_t aLdOff = (uint32_t)(((warpM * 64 + ((lane >> 3) & 1) * 8 + (lane & 7)) * LDSS
                                        + ((lane >> 4) & 1) * 4) * 4);
    const uint32_t bLdOff = (uint32_t)(A_FLOATS * 4
                                        + ((warpN * 32 + (lane & 7)) * LDSS
                                        + ((lane >> 3) & 1) * 4) * 4);

    for (;;) {
        if (tid == 0) s_tile = atomicAdd(ctr, 1);
        __syncthreads();                 // publishes s_tile; guards smem reuse vs prev epilogue
        const int tile = s_tile;
        if (tile >= nTiles) break;

        int rowTile, colTile, cblk;
        if (MODE == 0)      { cblk = tile & 15; rowTile = (tile >> 4) * BM; }
        else if (MODE == 1) { cblk = 15 - (tile >> 6); rowTile = (tile & 63) * BM; }
        else                { cblk = tile & 7;  rowTile = (tile >> 3) * BM; }
        colTile = cblk * BN;
        const int nIter = (MODE == 1) ? ((colTile + BN) / BK) : nIterFix;

        float acc[4][4][4];
        #pragma unroll
        for (int mt = 0; mt < 4; mt++)
            #pragma unroll
            for (int nt = 0; nt < 4; nt++)
                #pragma unroll
                for (int r = 0; r < 4; r++) acc[mt][nt][r] = 0.0f;

        #define ISSUE(it, s) do {                                                  \
            const int _k0 = (it) * BK;                                             \
            const float* _as = (MODE == 1 && _k0 < colTile) ? Ag2 : Ag;            \
            _Pragma("unroll")                                                      \
            for (int j = 0; j < 4; j++) {                                          \
                int f = tid + NTH * j;                                             \
                int r = f >> 3, q = f & 7;                                         \
                uint32_t d = sbase + (uint32_t)(s) * STAGE_BYTES + (uint32_t)(r * LDSS + q * 4) * 4; \
                cp16(d, _as + (size_t)(rowTile + r) * K + _k0 + q * 4);            \
            }                                                                      \
            _Pragma("unroll")                                                      \
            for (int j = 0; j < 4; j++) {                                          \
                int f = tid + NTH * j;                                             \
                int r = f >> 3, q = f & 7;                                         \
                uint32_t d = sbase + (uint32_t)(s) * STAGE_BYTES + (uint32_t)(A_FLOATS + r * LDSS + q * 4) * 4; \
                if (MODE == 2) {                                                   \
                    int gn = colTile + r;                                          \
                    uint32_t sz = (gn < OUT_F) ? 16u : 0u;                         \
                    const float* src = Bg + (size_t)(sz ? gn : 0) * K + _k0 + q * 4; \
                    cp16z(d, src, sz);                                             \
                } else {                                                           \
                    cp16(d, Bg + (size_t)(colTile + r) * K + _k0 + q * 4);         \
                }                                                                  \
            }                                                                      \
            cp_commit();                                                           \
        } while (0)

        ISSUE(0, 0);
        ISSUE(1, 1);

        int s = 0;
        for (int it = 0; it < nIter; ++it) {
            if (it + 1 < nIter) cp_wait<1>(); else cp_wait<0>();
            __syncthreads();             // data(it) visible; all warps done with MMA(it-1)
            if (it + 2 < nIter) ISSUE(it + 2, (s + 2) % NSTAGE);

            const uint32_t stageB = sbase + (uint32_t)s * STAGE_BYTES;
            const uint32_t aB = stageB + aLdOff;
            const uint32_t bB = stageB + bLdOff;
            #pragma unroll
            for (int kk = 0; kk < 4; kk++) {
                uint32_t af[4][4], bf[4][2];
                #pragma unroll
                for (int mt = 0; mt < 4; mt++)
                    ldsm_x4(af[mt], aB + (uint32_t)((mt * 16 * LDSS + kk * 8) * 4));
                #pragma unroll
                for (int nt = 0; nt < 4; nt++)
                    ldsm_x2(bf[nt], bB + (uint32_t)((nt * 8 * LDSS + kk * 8) * 4));
                #pragma unroll
                for (int mt = 0; mt < 4; mt++)
                    #pragma unroll
                    for (int nt = 0; nt < 4; nt++)
                        mma_tf32(acc[mt][nt], af[mt], bf[nt]);
            }
            s = (s + 1 == NSTAGE) ? 0 : s + 1;
        }
        __syncthreads();                 // all MMA reads done before epilogue smem reuse

        // ---------------- epilogues ----------------
        if (MODE == 0) {
            #pragma unroll
            for (int mt = 0; mt < 4; mt++)
                #pragma unroll
                for (int h = 0; h < 2; h++) {
                    const int R = rowTile + warpM * 64 + mt * 16 + g + h * 8;
                    float* op  = outp  + (size_t)R * RFF;
                    float* op2 = outp2 + (size_t)R * RFF;
                    #pragma unroll
                    for (int nt = 0; nt < 4; nt++) {
                        const int C = colTile + warpN * 32 + nt * 8 + 2 * t;
                        float2 bb = *(const float2*)(bias + C);
                        float2 o, o2;
                        o.x = to_tf32(cosf(acc[mt][nt][h * 2 + 0] + bb.x) * INV_RFF_SCALAR);
                        o.y = to_tf32(cosf(acc[mt][nt][h * 2 + 1] + bb.y) * INV_RFF_SCALAR);
                        o2.x = 2.0f * o.x; o2.y = 2.0f * o.y;
                        *(float2*)(op + C) = o;
                        *(float2*)(op2 + C) = o2;
                    }
                }
        } else if (MODE == 1) {
            float* red = dyn;  // [128][4]
            #pragma unroll
            for (int mt = 0; mt < 4; mt++)
                #pragma unroll
                for (int h = 0; h < 2; h++) {
                    const int lr = warpM * 64 + mt * 16 + g + h * 8;
                    const float* pr = phi + (size_t)(rowTile + lr) * RFF;
                    float sum = 0.0f;
                    #pragma unroll
                    for (int nt = 0; nt < 4; nt++) {
                        const int C = colTile + warpN * 32 + nt * 8 + 2 * t;
                        float2 p = *(const float2*)(pr + C);
                        sum = fmaf(acc[mt][nt][h * 2 + 0], p.x, sum);
                        sum = fmaf(acc[mt][nt][h * 2 + 1], p.y, sum);
                    }
                    sum += __shfl_xor_sync(0xffffffffu, sum, 1);
                    sum += __shfl_xor_sync(0xffffffffu, sum, 2);
                    if (t == 0) red[lr * 4 + warpN] = sum;
                }
            __syncthreads();
            if (tid < 128) {
                float sum = red[tid * 4 + 0] + red[tid * 4 + 1] + red[tid * 4 + 2] + red[tid * 4 + 3];
                diagp[(size_t)cblk * NROWS + rowTile + tid] = sum;
            }
        } else {
            float* scale = dyn;  // [128]
            if (tid < 128) {
                float dg = 0.0f;
                #pragma unroll
                for (int p = 0; p < 16; p++) dg += diagp[(size_t)p * NROWS + rowTile + tid];
                scale[tid] = rsqrtf(1.0f + MFF * dg);
            }
            __syncthreads();
            #pragma unroll
            for (int mt = 0; mt < 4; mt++)
                #pragma unroll
                for (int h = 0; h < 2; h++) {
                    const int lr = warpM * 64 + mt * 16 + g + h * 8;
                    const int R = rowTile + lr;
                    const float sc = scale[lr];
                    float* op = outp + (size_t)R * OUT_F;
                    #pragma unroll
                    for (int nt = 0; nt < 4; nt++) {
                        const int C = colTile + warpN * 32 + nt * 8 + 2 * t;
                        if (C < OUT_F) {
                            float2 bb = *(const float2*)(bias + C);
                            float2 o;
                            o.x = (acc[mt][nt][h * 2 + 0] + bb.x) * sc;
                            o.y = (acc[mt][nt][h * 2 + 1] + bb.y) * sc;
                            *(float2*)(op + C) = o;
                        }
                    }
                }
        }
        #undef ISSUE
    }
}

// ---------------- host ----------------
extern "C" void kernel_launch(void* const* d_in, const int* in_sizes, int n_in,
                              void* d_out, int out_size)
{
    const float* D   = (const float*)d_in[0];
    const float* W   = (const float*)d_in[1];
    const float* b   = (const float*)d_in[2];
    const float* lw  = (const float*)d_in[3];
    const float* lb  = (const float*)d_in[4];
    const float* cov = (const float*)d_in[5];
    float* out = (float*)d_out;

    float *Phi, *Phi2, *Abig, *Bbig, *diagp;
    int* ctr;
    cudaGetSymbolAddress((void**)&Phi,   g_Phi);
    cudaGetSymbolAddress((void**)&Phi2,  g_Phi2);
    cudaGetSymbolAddress((void**)&Abig,  g_Abig);
    cudaGetSymbolAddress((void**)&Bbig,  g_Bbig);
    cudaGetSymbolAddress((void**)&diagp, g_diag_part);
    cudaGetSymbolAddress((void**)&ctr,   g_ctr);

    const int smem = NSTAGE * STAGE_BYTES;  // 110592 bytes
    cudaFuncSetAttribute(gp_mma<0>, cudaFuncAttributeMaxDynamicSharedMemorySize, smem);
    cudaFuncSetAttribute(gp_mma<1>, cudaFuncAttributeMaxDynamicSharedMemorySize, smem);
    cudaFuncSetAttribute(gp_mma<2>, cudaFuncAttributeMaxDynamicSharedMemorySize, smem);

    cudaMemsetAsync(ctr, 0, 4 * sizeof(int));

    // prep: tf32 hi/lo split operands (GEMM1 only)
    split_D_k<<<(NROWS * IN_F + 255) / 256, 256>>>(D, Abig);
    split_W_k<<<dim3(RFF / 32, IN_F / 32), dim3(32, 8)>>>(W, Bbig);

    // GEMM1: Phi (+Phi2=2*Phi) = tf32(cos(D@W+b)/32), split-tf32, K=1536, 1024 tiles
    gp_mma<0><<<GRID_P, NTH, smem>>>(
        Abig, nullptr, Bbig, b, Phi, Phi2, nullptr, nullptr,
        ctr + 0, 1024, KBIG, KBIG / BK);
    // GEMM2: triangular diag partials; A in {Phi2, Phi}, B = raw cov; 1024 tiles LPT
    gp_mma<1><<<GRID_P, NTH, smem>>>(
        Phi, Phi2, cov, nullptr, nullptr, nullptr, Phi, diagp,
        ctr + 1, 1024, RFF, 0);
    // GEMM3: out = (Phi@lw^T + lb) * rsqrt(1+25*diag); B = raw lw zero-padded; 512 tiles
    gp_mma<2><<<GRID_P, NTH, smem>>>(
        Phi, nullptr, lw, lb, out, nullptr, nullptr, diagp,
        ctr + 2, 512, RFF, RFF / BK);
}